// round 2
// baseline (speedup 1.0000x reference)
#include <cuda_runtime.h>

// Router: alpha = softmax(topk_mask(z @ W^T + b))
// z: [N=8192, D=4096] f32, W: [K=64, D] f32, b: [K] f32, k: int (=2)

namespace {
typedef unsigned long long ull;
constexpr int Dc = 4096;
constexpr int Kc = 64;
constexpr int BM = 32;        // rows per CTA
constexpr int BK = 32;        // d-chunk
constexpr int NTHREADS = 128;
constexpr int ZSTR = BK + 1;  // zs stride in float2 units (pad: banks spread)
constexpr int WSTR = Kc + 8;  // wsT stride in floats
constexpr int ZBUF = BM * ZSTR;        // float2 count per z buffer (1056)
constexpr int WBUF = BK * WSTR;        // float  count per w buffer (2304)

__device__ __forceinline__ ull pk2(float x, float y) {
    ull r;
    asm("mov.b64 %0, {%1, %2};" : "=l"(r) : "f"(x), "f"(y));
    return r;
}
__device__ __forceinline__ float2 upk2(ull v) {
    float2 r;
    asm("mov.b64 {%0, %1}, %2;" : "=f"(r.x), "=f"(r.y) : "l"(v));
    return r;
}
__device__ __forceinline__ void ffma2(ull& d, ull a, ull b) {
    asm("fma.rn.f32x2 %0, %1, %2, %3;" : "=l"(d) : "l"(a), "l"(b), "l"(d));
}
} // namespace

__global__ __launch_bounds__(NTHREADS, 4) void router_kernel(
    const float* __restrict__ z, const float* __restrict__ W,
    const float* __restrict__ b, const int* __restrict__ kptr,
    float* __restrict__ out)
{
    // Layout (floats): [zbuf0 (2*ZBUF)] [zbuf1 (2*ZBUF)] [wbuf0 (WBUF)] [wbuf1 (WBUF)]
    __shared__ __align__(16) float smem[4 * ZBUF + 2 * WBUF];
    float2* const zsB[2] = { (float2*)smem, (float2*)smem + ZBUF };
    float*  const wsB[2] = { smem + 4 * ZBUF, smem + 4 * ZBUF + WBUF };

    const int tid  = threadIdx.x;
    const int row0 = blockIdx.x * BM;
    const int tx = tid & 7;    // col group: cols [tx*8, tx*8+8)
    const int ty = tid >> 3;   // 0..15 -> rows ty*2, ty*2+1

    ull acc[2][4];
#pragma unroll
    for (int j = 0; j < 2; ++j)
#pragma unroll
        for (int i = 0; i < 4; ++i) acc[j][i] = 0ull;

    // Per-tile loads: z tile 32x32 (2 float4/thr), W tile 64x32 (4 float4/thr).
    const int zr = tid >> 3;        // 0..15 (and +16)
    const int zc = (tid & 7) * 4;

    float4 pz0, pz1, pw0, pw1, pw2, pw3;

#define LOAD_TILE(dBase)                                                       \
    do {                                                                       \
        pz0 = *(const float4*)(z + (size_t)(row0 + zr) * Dc + (dBase) + zc);   \
        pz1 = *(const float4*)(z + (size_t)(row0 + zr + 16) * Dc + (dBase) + zc); \
        pw0 = *(const float4*)(W + (size_t)(zr +  0) * Dc + (dBase) + zc);     \
        pw1 = *(const float4*)(W + (size_t)(zr + 16) * Dc + (dBase) + zc);     \
        pw2 = *(const float4*)(W + (size_t)(zr + 32) * Dc + (dBase) + zc);     \
        pw3 = *(const float4*)(W + (size_t)(zr + 48) * Dc + (dBase) + zc);     \
    } while (0)

#define STORE_TILE(buf)                                                        \
    do {                                                                       \
        float2* zp = zsB[buf] + zr * ZSTR + zc;                                \
        zp[0] = make_float2(pz0.x, pz0.x);                                     \
        zp[1] = make_float2(pz0.y, pz0.y);                                     \
        zp[2] = make_float2(pz0.z, pz0.z);                                     \
        zp[3] = make_float2(pz0.w, pz0.w);                                     \
        zp = zsB[buf] + (zr + 16) * ZSTR + zc;                                 \
        zp[0] = make_float2(pz1.x, pz1.x);                                     \
        zp[1] = make_float2(pz1.y, pz1.y);                                     \
        zp[2] = make_float2(pz1.z, pz1.z);                                     \
        zp[3] = make_float2(pz1.w, pz1.w);                                     \
        float* wp = wsB[buf];                                                  \
        wp[(zc + 0) * WSTR + zr +  0] = pw0.x;                                 \
        wp[(zc + 1) * WSTR + zr +  0] = pw0.y;                                 \
        wp[(zc + 2) * WSTR + zr +  0] = pw0.z;                                 \
        wp[(zc + 3) * WSTR + zr +  0] = pw0.w;                                 \
        wp[(zc + 0) * WSTR + zr + 16] = pw1.x;                                 \
        wp[(zc + 1) * WSTR + zr + 16] = pw1.y;                                 \
        wp[(zc + 2) * WSTR + zr + 16] = pw1.z;                                 \
        wp[(zc + 3) * WSTR + zr + 16] = pw1.w;                                 \
        wp[(zc + 0) * WSTR + zr + 32] = pw2.x;                                 \
        wp[(zc + 1) * WSTR + zr + 32] = pw2.y;                                 \
        wp[(zc + 2) * WSTR + zr + 32] = pw2.z;                                 \
        wp[(zc + 3) * WSTR + zr + 32] = pw2.w;                                 \
        wp[(zc + 0) * WSTR + zr + 48] = pw3.x;                                 \
        wp[(zc + 1) * WSTR + zr + 48] = pw3.y;                                 \
        wp[(zc + 2) * WSTR + zr + 48] = pw3.z;                                 \
        wp[(zc + 3) * WSTR + zr + 48] = pw3.w;                                 \
    } while (0)

    constexpr int T = Dc / BK;  // 128 tiles
    LOAD_TILE(0);
    STORE_TILE(0);
    __syncthreads();

    const float2* zrow0 = (const float2*)zsB[0] + (ty * 2 + 0) * ZSTR;
    const float2* zrow1 = (const float2*)zsB[0] + (ty * 2 + 1) * ZSTR;
    const ptrdiff_t zbufStep = ZBUF;  // float2 units between buffers

    for (int t = 0; t < T; ++t) {
        const int cur = t & 1;
        const bool has_next = (t + 1 < T);
        if (has_next) LOAD_TILE((t + 1) * BK);  // LDGs in flight during compute

        const float2* z0 = zrow0 + cur * zbufStep;
        const float2* z1 = zrow1 + cur * zbufStep;
        const float*  wb_ = wsB[cur] + tx * 8;

#pragma unroll
        for (int d = 0; d < BK; ++d) {
            const ull A0 = *(const ull*)(z0 + d);
            const ull A1 = *(const ull*)(z1 + d);
            const float4 wa = *(const float4*)(wb_ + d * WSTR);
            const float4 wc = *(const float4*)(wb_ + d * WSTR + 4);
            const ull w0 = pk2(wa.x, wa.y);
            const ull w1 = pk2(wa.z, wa.w);
            const ull w2 = pk2(wc.x, wc.y);
            const ull w3 = pk2(wc.z, wc.w);
            ffma2(acc[0][0], A0, w0); ffma2(acc[0][1], A0, w1);
            ffma2(acc[0][2], A0, w2); ffma2(acc[0][3], A0, w3);
            ffma2(acc[1][0], A1, w0); ffma2(acc[1][1], A1, w1);
            ffma2(acc[1][2], A1, w2); ffma2(acc[1][3], A1, w3);
        }

        if (has_next) STORE_TILE(1 - cur);
        __syncthreads();
    }

    // ---- Epilogue: logits tile -> top-k mask -> softmax ----
    float* lg = smem;  // [BM][Kc+1]
#pragma unroll
    for (int j = 0; j < 2; ++j) {
        const int row = ty * 2 + j;
        const int col = tx * 8;
#pragma unroll
        for (int i = 0; i < 4; ++i) {
            const float2 v = upk2(acc[j][i]);
            lg[row * (Kc + 1) + col + 2 * i + 0] = v.x + b[col + 2 * i + 0];
            lg[row * (Kc + 1) + col + 2 * i + 1] = v.y + b[col + 2 * i + 1];
        }
    }
    __syncthreads();

    if (tid < BM) {
        int kk = kptr ? *kptr : 2;
        if (kk < 1) kk = 1;
        if (kk > Kc) kk = Kc;

        float* r = lg + tid * (Kc + 1);

        // k passes of argmax; strict '>' keeps lowest index on ties,
        // matching jax.lax.top_k tie-breaking.
        ull sel = 0ull;
        float m = 0.f;
        for (int p = 0; p < kk; ++p) {
            float best = -3.4e38f;
            int bi = 0;
            for (int c = 0; c < Kc; ++c) {
                const float v = r[c];
                const bool taken = (sel >> c) & 1ull;
                if (!taken && v > best) { best = v; bi = c; }
            }
            sel |= (1ull << bi);
            if (p == 0) m = best;  // top-1 == max of sparse logits
        }

        // softmax over sparse logits; non-selected entries exactly 0
        // (matches expf(logit - max - 1e9) fp32 underflow).
        float sum = 0.f;
        for (int c = 0; c < Kc; ++c) {
            const float e = ((sel >> c) & 1ull) ? expf(r[c] - m) : 0.f;
            r[c] = e;
            sum += e;
        }
        const float inv = 1.0f / sum;
        float* o = out + (size_t)(row0 + tid) * Kc;
        for (int c = 0; c < Kc; ++c) o[c] = r[c] * inv;
    }
#undef LOAD_TILE
#undef STORE_TILE
}

extern "C" void kernel_launch(void* const* d_in, const int* in_sizes, int n_in,
                              void* d_out, int out_size) {
    const float* z = (const float*)d_in[0];
    const float* W = (const float*)d_in[1];
    const float* b = (const float*)d_in[2];
    const int* kp = (n_in > 3) ? (const int*)d_in[3] : nullptr;
    float* out = (float*)d_out;

    const int N = in_sizes[0] / Dc;  // 8192
    router_kernel<<<N / BM, NTHREADS>>>(z, W, b, kp, out);
    (void)out_size;
}

// round 4
// speedup vs baseline: 2.2622x; 2.2622x over previous
#include <cuda_runtime.h>
#include <cstdint>

// Router: alpha = softmax(topk_mask(z @ W^T + b))
// z: [8192, 4096] f32, W: [64, 4096] f32, b: [64] f32, k: int (=2)
// GEMM via mma.sync m16n8k8 tf32 (portable PTX), 3xTF32 hi/lo split for
// fp32-class accuracy, fused top-k + softmax epilogue.

namespace {
constexpr int Dc = 4096;
constexpr int Kc = 64;       // experts (N)
constexpr int BM = 64;       // rows per CTA
constexpr int BK = 32;       // k per stage
constexpr int STR = 36;      // smem row stride (floats): bank = (4r+k)%32, conflict-free
constexpr int TILE = 64 * STR;               // floats per tile (A uses 64 rows, B 64 rows)
constexpr int STAGE_F = 4 * TILE;            // Ah, Al, Bh, Bl
constexpr int SMEM_BYTES = 2 * STAGE_F * 4;  // 73728
constexpr int NTHREADS = 256;
constexpr int T_STAGES = Dc / BK;            // 128

__device__ __forceinline__ float tf32r(float x) {
    float r;
    asm("cvt.rna.tf32.f32 %0, %1;" : "=f"(r) : "f"(x));
    return r;
}
__device__ __forceinline__ void mma8(float* d, uint32_t a0, uint32_t a1,
                                     uint32_t a2, uint32_t a3,
                                     uint32_t b0, uint32_t b1) {
    asm volatile(
        "mma.sync.aligned.m16n8k8.row.col.f32.tf32.tf32.f32 "
        "{%0,%1,%2,%3}, {%4,%5,%6,%7}, {%8,%9}, {%0,%1,%2,%3};"
        : "+f"(d[0]), "+f"(d[1]), "+f"(d[2]), "+f"(d[3])
        : "r"(a0), "r"(a1), "r"(a2), "r"(a3), "r"(b0), "r"(b1));
}
__device__ __forceinline__ uint32_t f2u(float x) { return __float_as_uint(x); }

__device__ __forceinline__ void split4(float4 v, float4& h, float4& l) {
    h.x = tf32r(v.x); l.x = tf32r(v.x - h.x);
    h.y = tf32r(v.y); l.y = tf32r(v.y - h.y);
    h.z = tf32r(v.z); l.z = tf32r(v.z - h.z);
    h.w = tf32r(v.w); l.w = tf32r(v.w - h.w);
}
} // namespace

extern __shared__ __align__(16) float smem[];

__global__ __launch_bounds__(NTHREADS, 1) void router_mma_kernel(
    const float* __restrict__ z, const float* __restrict__ W,
    const float* __restrict__ b, const int* __restrict__ kptr,
    float* __restrict__ out)
{
    const int tid = threadIdx.x;
    const int wid = tid >> 5;
    const int lane = tid & 31;
    const int row0 = blockIdx.x * BM;

    // tiles within a stage
    float* const stg[2] = { smem, smem + STAGE_F };
    constexpr int AH = 0, AL = TILE, BH = 2 * TILE, BL = 3 * TILE;

    // ---- producer indexing: thread covers one row-segment of 8 cols ----
    const int pr = tid >> 2;            // 0..63 (z row within tile / W row)
    const int pc = (tid & 3) * 8;       // 0,8,16,24
    const float* zg = z + (size_t)(row0 + pr) * Dc + pc;
    const float* wg = W + (size_t)pr * Dc + pc;
    const int psmem = pr * STR + pc;    // float index; 16B aligned

    // ---- consumer indexing ----
    const int ms = wid & 3;             // m-slice: rows 16*ms..
    const int nh = wid >> 2;            // n-half: cols 32*nh..
    const int g = lane >> 2;            // 0..7
    const int kk = lane & 3;            // 0..3

    float acc[4][4];
#pragma unroll
    for (int i = 0; i < 4; ++i)
#pragma unroll
        for (int j = 0; j < 4; ++j) acc[i][j] = 0.f;

    float4 vz0, vz1, vw0, vw1;

#define LDG_STAGE(t)                                   \
    do {                                               \
        const int kb = (t) * BK;                       \
        vz0 = *(const float4*)(zg + kb);               \
        vz1 = *(const float4*)(zg + kb + 4);           \
        vw0 = *(const float4*)(wg + kb);               \
        vw1 = *(const float4*)(wg + kb + 4);           \
    } while (0)

#define STS_STAGE(buf)                                 \
    do {                                               \
        float* s_ = stg[buf];                          \
        float4 h, l;                                   \
        split4(vz0, h, l);                             \
        *(float4*)(s_ + AH + psmem)     = h;           \
        *(float4*)(s_ + AL + psmem)     = l;           \
        split4(vz1, h, l);                             \
        *(float4*)(s_ + AH + psmem + 4) = h;           \
        *(float4*)(s_ + AL + psmem + 4) = l;           \
        split4(vw0, h, l);                             \
        *(float4*)(s_ + BH + psmem)     = h;           \
        *(float4*)(s_ + BL + psmem)     = l;           \
        split4(vw1, h, l);                             \
        *(float4*)(s_ + BH + psmem + 4) = h;           \
        *(float4*)(s_ + BL + psmem + 4) = l;           \
    } while (0)

    LDG_STAGE(0);
    STS_STAGE(0);
    __syncthreads();

    // per-thread fragment base pointers (row part), k-offset added per chunk
    const int arow = (ms * 16 + g) * STR + kk;   // a0; a1 at +8*STR; a2 at +4
    // B fragment: col n = nh*32 + nb*8 + g ; k = kc + kk (b0), +4 (b1)
    const int brow = (nh * 32 + g) * STR + kk;

    for (int t = 0; t < T_STAGES; ++t) {
        const int cur = t & 1;
        const bool has_next = (t + 1 < T_STAGES);
        if (has_next) LDG_STAGE(t + 1);

        const float* s_ = stg[cur];
        const float* ah_ = s_ + AH + arow;
        const float* al_ = s_ + AL + arow;
        const float* bh_ = s_ + BH + brow;
        const float* bl_ = s_ + BL + brow;

#pragma unroll
        for (int c = 0; c < 4; ++c) {
            const int kc = c * 8;
            const uint32_t ah0 = f2u(ah_[kc]);
            const uint32_t ah1 = f2u(ah_[kc + 8 * STR]);
            const uint32_t ah2 = f2u(ah_[kc + 4]);
            const uint32_t ah3 = f2u(ah_[kc + 8 * STR + 4]);
            const uint32_t al0 = f2u(al_[kc]);
            const uint32_t al1 = f2u(al_[kc + 8 * STR]);
            const uint32_t al2 = f2u(al_[kc + 4]);
            const uint32_t al3 = f2u(al_[kc + 8 * STR + 4]);
#pragma unroll
            for (int nb = 0; nb < 4; ++nb) {
                const int bo = nb * 8 * STR + kc;
                const uint32_t bh0 = f2u(bh_[bo]);
                const uint32_t bh1 = f2u(bh_[bo + 4]);
                const uint32_t bl0 = f2u(bl_[bo]);
                const uint32_t bl1 = f2u(bl_[bo + 4]);
                mma8(acc[nb], ah0, ah1, ah2, ah3, bh0, bh1);
                mma8(acc[nb], ah0, ah1, ah2, ah3, bl0, bl1);
                mma8(acc[nb], al0, al1, al2, al3, bh0, bh1);
            }
        }
        __syncthreads();
        if (has_next) {
            STS_STAGE(1 - cur);
            __syncthreads();
        }
    }

    // ---- epilogue: logits -> top-k -> softmax ----
    float* lg = smem;  // [64][65] overlay
    {
        const int grow = ms * 16 + g;
#pragma unroll
        for (int nb = 0; nb < 4; ++nb) {
            const int col = nh * 32 + nb * 8 + kk * 2;
            lg[grow * 65 + col]           = acc[nb][0] + b[col];
            lg[grow * 65 + col + 1]       = acc[nb][1] + b[col + 1];
            lg[(grow + 8) * 65 + col]     = acc[nb][2] + b[col];
            lg[(grow + 8) * 65 + col + 1] = acc[nb][3] + b[col + 1];
        }
    }
    __syncthreads();

    if (tid < BM) {
        int kk_ = kptr ? *kptr : 2;
        if (kk_ < 1) kk_ = 1;
        if (kk_ > Kc) kk_ = Kc;
        float* r = lg + tid * 65;

        // k argmax passes; strict '>' keeps lowest index on ties (jax.lax.top_k)
        unsigned long long sel = 0ull;
        float m = 0.f;
        for (int p = 0; p < kk_; ++p) {
            float best = -3.4e38f;
            int bi = 0;
            for (int c = 0; c < Kc; ++c) {
                const float v = r[c];
                const bool taken = (sel >> c) & 1ull;
                if (!taken && v > best) { best = v; bi = c; }
            }
            sel |= (1ull << bi);
            if (p == 0) m = best;
        }
        float sum = 0.f;
        float ev[Kc];
        for (int c = 0; c < Kc; ++c) {
            const float e = ((sel >> c) & 1ull) ? expf(r[c] - m) : 0.f;
            ev[c] = e;
            sum += e;
        }
        const float inv = 1.0f / sum;
        float* o = out + (size_t)(row0 + tid) * Kc;
        for (int c = 0; c < Kc; ++c) o[c] = ev[c] * inv;
    }
#undef LDG_STAGE
#undef STS_STAGE
}

extern "C" void kernel_launch(void* const* d_in, const int* in_sizes, int n_in,
                              void* d_out, int out_size) {
    const float* z = (const float*)d_in[0];
    const float* W = (const float*)d_in[1];
    const float* b = (const float*)d_in[2];
    const int* kp = (n_in > 3) ? (const int*)d_in[3] : nullptr;
    float* out = (float*)d_out;

    cudaFuncSetAttribute(router_mma_kernel,
                         cudaFuncAttributeMaxDynamicSharedMemorySize, SMEM_BYTES);
    const int N = in_sizes[0] / Dc;  // 8192
    router_mma_kernel<<<N / BM, NTHREADS, SMEM_BYTES>>>(z, W, b, kp, out);
    (void)out_size;
}

// round 5
// speedup vs baseline: 3.7772x; 1.6697x over previous
#include <cuda_runtime.h>
#include <cstdint>

// Router: alpha = softmax(topk_mask(z @ W^T + b))
// z: [8192,4096] f32, W: [64,4096] f32, b:[64] f32, k=2
// mma.sync m16n8k8 tf32 (3xTF32 split), ldmatrix fragment feed,
// 512 threads/CTA, fused top-k + softmax.

namespace {
constexpr int Dc = 4096;
constexpr int Kc = 64;
constexpr int BM = 64;
constexpr int BK = 32;
constexpr int STR = 36;                  // floats; bank-conflict-free, 144B rows
constexpr int TILE = 64 * STR;           // 2304 floats per tile
constexpr int STAGE_F = 4 * TILE;        // Ah Al Bh Bl
constexpr int SMEM_BYTES = 2 * STAGE_F * 4;  // 73728
constexpr int NTHREADS = 512;
constexpr int T_STAGES = Dc / BK;        // 128

__device__ __forceinline__ float tf32r(float x) {
    float r;
    asm("cvt.rna.tf32.f32 %0, %1;" : "=f"(r) : "f"(x));
    return r;
}
__device__ __forceinline__ void mma8(float* d, const uint32_t* a,
                                     uint32_t b0, uint32_t b1) {
    asm volatile(
        "mma.sync.aligned.m16n8k8.row.col.f32.tf32.tf32.f32 "
        "{%0,%1,%2,%3}, {%4,%5,%6,%7}, {%8,%9}, {%0,%1,%2,%3};"
        : "+f"(d[0]), "+f"(d[1]), "+f"(d[2]), "+f"(d[3])
        : "r"(a[0]), "r"(a[1]), "r"(a[2]), "r"(a[3]), "r"(b0), "r"(b1));
}
__device__ __forceinline__ void ldsm4(uint32_t* r, uint32_t addr) {
    asm volatile(
        "ldmatrix.sync.aligned.m8n8.x4.shared.b16 {%0,%1,%2,%3}, [%4];"
        : "=r"(r[0]), "=r"(r[1]), "=r"(r[2]), "=r"(r[3]) : "r"(addr));
}
__device__ __forceinline__ uint32_t smem_u32(const void* p) {
    uint32_t a;
    asm("{ .reg .u64 t; cvta.to.shared.u64 t, %1; cvt.u32.u64 %0, t; }"
        : "=r"(a) : "l"(p));
    return a;
}
// hi = tf32(v); lo = v - hi (exact in fp32; <=13 sig bits so tf32-safe raw)
__device__ __forceinline__ void split4(float4 v, float4& h, float4& l) {
    h.x = tf32r(v.x); l.x = v.x - h.x;
    h.y = tf32r(v.y); l.y = v.y - h.y;
    h.z = tf32r(v.z); l.z = v.z - h.z;
    h.w = tf32r(v.w); l.w = v.w - h.w;
}
} // namespace

extern __shared__ __align__(16) float smem[];

__global__ __launch_bounds__(NTHREADS, 1) void router_mma_kernel(
    const float* __restrict__ z, const float* __restrict__ W,
    const float* __restrict__ b, const int* __restrict__ kptr,
    float* __restrict__ out)
{
    const int tid = threadIdx.x;
    const int wid = tid >> 5;
    const int lane = tid & 31;
    const int row0 = blockIdx.x * BM;

    // ---- producer mapping: 1 z float4 + 1 W float4 per thread per stage ----
    const int pr = tid >> 3;            // 0..63
    const int pc = (tid & 7) * 4;       // 0..28
    const float* zg = z + (size_t)(row0 + pr) * Dc + pc;
    const float* wg = W + (size_t)pr * Dc + pc;
    const int psmem = pr * STR + pc;

    // ---- consumer mapping: warp = m-slice (wid&3) x n-block16 (wid>>2) ----
    const int ms = wid & 3;
    const int nh = wid >> 2;
    // ldmatrix lane->row/koff (identical formula for A and B x4 loads)
    const int m4 = lane >> 3;                       // matrix id
    const int mrow = ((m4 & 1) << 3) + (lane & 7);  // row within 16-row slab
    const int kofs = (m4 >> 1) * 4;                 // float col offset 0/4

    const uint32_t sb = smem_u32(smem);
    const uint32_t aH0 = sb + (uint32_t)(((ms * 16 + mrow) * STR + kofs) * 4);
    const uint32_t bH0 = sb + (uint32_t)((2 * TILE + (nh * 16 + mrow) * STR + kofs) * 4);
    constexpr uint32_t LO = TILE * 4;               // byte offset hi->lo tile
    constexpr uint32_t SSO = STAGE_F * 4;           // byte offset stage0->stage1

    float acc[2][4];
#pragma unroll
    for (int i = 0; i < 2; ++i)
#pragma unroll
        for (int j = 0; j < 4; ++j) acc[i][j] = 0.f;

    float4 vz, vw;

#define LDG_STAGE(t)                                \
    do {                                            \
        vz = *(const float4*)(zg + (t) * BK);       \
        vw = *(const float4*)(wg + (t) * BK);       \
    } while (0)

#define STS_STAGE(buf)                              \
    do {                                            \
        float* s_ = smem + (buf) * STAGE_F;         \
        float4 h, l;                                \
        split4(vz, h, l);                           \
        *(float4*)(s_ + psmem)            = h;      \
        *(float4*)(s_ + TILE + psmem)     = l;      \
        split4(vw, h, l);                           \
        *(float4*)(s_ + 2 * TILE + psmem) = h;      \
        *(float4*)(s_ + 3 * TILE + psmem) = l;      \
    } while (0)

    LDG_STAGE(0);
    STS_STAGE(0);
    __syncthreads();

    for (int t = 0; t < T_STAGES; ++t) {
        const int cur = t & 1;
        const bool has_next = (t + 1 < T_STAGES);
        if (has_next) LDG_STAGE(t + 1);

        const uint32_t so = cur ? SSO : 0u;
#pragma unroll
        for (int c = 0; c < 4; ++c) {
            const uint32_t co = c * 32;  // 8 floats per chunk
            uint32_t ah[4], al[4], bh[4], bl[4];
            ldsm4(ah, aH0 + so + co);
            ldsm4(al, aH0 + so + LO + co);
            ldsm4(bh, bH0 + so + co);
            ldsm4(bl, bH0 + so + LO + co);
            // x4 B regs: {b0 of nb0, b0 of nb1, b1 of nb0, b1 of nb1}
            mma8(acc[0], ah, bh[0], bh[2]);
            mma8(acc[0], ah, bl[0], bl[2]);
            mma8(acc[0], al, bh[0], bh[2]);
            mma8(acc[1], ah, bh[1], bh[3]);
            mma8(acc[1], ah, bl[1], bl[3]);
            mma8(acc[1], al, bh[1], bh[3]);
        }

        if (has_next) STS_STAGE(1 - cur);
        __syncthreads();
    }

    // ---- epilogue: logits -> top-k -> softmax ----
    float* lg = smem;  // [64][65] overlay on stage 0
    {
        const int g = lane >> 2;
        const int tk = lane & 3;
        const int grow = ms * 16 + g;
#pragma unroll
        for (int nb = 0; nb < 2; ++nb) {
            const int col = nh * 16 + nb * 8 + tk * 2;
            lg[grow * 65 + col]           = acc[nb][0] + b[col];
            lg[grow * 65 + col + 1]       = acc[nb][1] + b[col + 1];
            lg[(grow + 8) * 65 + col]     = acc[nb][2] + b[col];
            lg[(grow + 8) * 65 + col + 1] = acc[nb][3] + b[col + 1];
        }
    }
    __syncthreads();

    if (tid < BM) {
        int kk = kptr ? *kptr : 2;
        if (kk < 1) kk = 1;
        if (kk > Kc) kk = Kc;
        float* r = lg + tid * 65;

        // k argmax passes; strict '>' keeps lowest index on ties (jax.lax.top_k)
        unsigned long long sel = 0ull;
        float m = 0.f;
        for (int p = 0; p < kk; ++p) {
            float best = -3.4e38f;
            int bi = 0;
            for (int c = 0; c < Kc; ++c) {
                const float v = r[c];
                const bool taken = (sel >> c) & 1ull;
                if (!taken && v > best) { best = v; bi = c; }
            }
            sel |= (1ull << bi);
            if (p == 0) m = best;
        }
        float sum = 0.f;
        float ev[Kc];
        for (int c = 0; c < Kc; ++c) {
            const float e = ((sel >> c) & 1ull) ? expf(r[c] - m) : 0.f;
            ev[c] = e;
            sum += e;
        }
        const float inv = 1.0f / sum;
        float* o = out + (size_t)(row0 + tid) * Kc;
        for (int c = 0; c < Kc; ++c) o[c] = ev[c] * inv;
    }
#undef LDG_STAGE
#undef STS_STAGE
}

extern "C" void kernel_launch(void* const* d_in, const int* in_sizes, int n_in,
                              void* d_out, int out_size) {
    const float* z = (const float*)d_in[0];
    const float* W = (const float*)d_in[1];
    const float* b = (const float*)d_in[2];
    const int* kp = (n_in > 3) ? (const int*)d_in[3] : nullptr;
    float* out = (float*)d_out;

    cudaFuncSetAttribute(router_mma_kernel,
                         cudaFuncAttributeMaxDynamicSharedMemorySize, SMEM_BYTES);
    const int N = in_sizes[0] / Dc;  // 8192
    router_mma_kernel<<<N / BM, NTHREADS, SMEM_BYTES>>>(z, W, b, kp, out);
    (void)out_size;
}

// round 6
// speedup vs baseline: 5.0408x; 1.3345x over previous
#include <cuda_runtime.h>
#include <cuda_fp16.h>
#include <cstdint>

// Router: alpha = softmax(topk_mask(z @ W^T + b))
// z:[8192,4096]f32  W:[64,4096]f32  b:[64]f32  k=2
// Kernel 1: split-K GEMM, fp16 2-tier split (z=z1+z2, 64W=w1+w2),
//           mma.sync m16n8k16 f16->f32; partial logits to scratch.
// Kernel 2: reduce halves, *1/64, +bias, top-k mask, softmax.

namespace {
typedef uint32_t u32;
constexpr int D = 4096;
constexpr int KSPLIT = 2;
constexpr int KH = D / KSPLIT;       // 2048
constexpr int BM = 128;
constexpr int BK = 32;
constexpr int NSTG = KH / BK;        // 64
constexpr int NT1 = 512;             // 16 warps
constexpr int Kc = 64;
constexpr int NROWS = 8192;

// smem: per tier tile row = 32 halfs data + 8 pad = 40 halfs (80B) -> ldmatrix
// rows hit distinct bank groups ((20r)%32 distinct for r=0..7).
constexpr int ROWB = 80;                       // bytes per row
constexpr int A1_OFF = 0;                      // A tier1: 128*80 = 10240B
constexpr int A2_OFF = 10240;
constexpr int B1_OFF = 20480;                  // B tier1: 64*80 = 5120B
constexpr int B2_OFF = 25600;
constexpr int STG_B = 30720;                   // bytes per stage
constexpr int SMEM1 = 2 * STG_B;               // 61440

__device__ float g_part[KSPLIT * NROWS * Kc];  // 4MB scratch

__device__ __forceinline__ void mma16(float* d, const u32* a, u32 b0, u32 b1) {
    asm volatile(
        "mma.sync.aligned.m16n8k16.row.col.f32.f16.f16.f32 "
        "{%0,%1,%2,%3}, {%4,%5,%6,%7}, {%8,%9}, {%0,%1,%2,%3};"
        : "+f"(d[0]), "+f"(d[1]), "+f"(d[2]), "+f"(d[3])
        : "r"(a[0]), "r"(a[1]), "r"(a[2]), "r"(a[3]), "r"(b0), "r"(b1));
}
__device__ __forceinline__ void ldsm4(u32* r, u32 addr) {
    asm volatile(
        "ldmatrix.sync.aligned.m8n8.x4.shared.b16 {%0,%1,%2,%3}, [%4];"
        : "=r"(r[0]), "=r"(r[1]), "=r"(r[2]), "=r"(r[3]) : "r"(addr));
}
__device__ __forceinline__ u32 smem_u32(const void* p) {
    u32 a;
    asm("{ .reg .u64 t; cvta.to.shared.u64 t, %1; cvt.u32.u64 %0, t; }"
        : "=r"(a) : "l"(p));
    return a;
}
// 2-tier split: h1 = rn(v), h2 = rn(v - h1). v = h1 + h2 + O(2^-22 |v|).
__device__ __forceinline__ void split_pack(float4 v, uint2& t1, uint2& t2) {
    __half hx = __float2half_rn(v.x), hy = __float2half_rn(v.y),
           hz = __float2half_rn(v.z), hw = __float2half_rn(v.w);
    float rx = v.x - __half2float(hx), ry = v.y - __half2float(hy),
          rz = v.z - __half2float(hz), rw = v.w - __half2float(hw);
    __half lx = __float2half_rn(rx), ly = __float2half_rn(ry),
           lz = __float2half_rn(rz), lw = __float2half_rn(rw);
    t1.x = (u32)__half_as_ushort(hx) | ((u32)__half_as_ushort(hy) << 16);
    t1.y = (u32)__half_as_ushort(hz) | ((u32)__half_as_ushort(hw) << 16);
    t2.x = (u32)__half_as_ushort(lx) | ((u32)__half_as_ushort(ly) << 16);
    t2.y = (u32)__half_as_ushort(lz) | ((u32)__half_as_ushort(lw) << 16);
}
} // namespace

extern __shared__ __align__(16) char smem1[];

__global__ __launch_bounds__(NT1, 1) void router_gemm_kernel(
    const float* __restrict__ z, const float* __restrict__ W)
{
    const int tid = threadIdx.x;
    const int wid = tid >> 5;
    const int lane = tid & 31;
    const int rb = blockIdx.x >> 1;       // row block
    const int ks = blockIdx.x & 1;        // k half
    const int row0 = rb * BM;
    const int kbase = ks * KH;

    // ---- producer mapping ----
    // A: slots tid and tid+512 -> row = slot>>3 (0..127), kg = slot&7 (k = kg*4)
    // B: slot tid -> row = tid>>3 (0..63), kg = tid&7
    const int ar = tid >> 3;              // 0..63 ; second A row = ar+64
    const int kg = tid & 7;
    const float* zg0 = z + (size_t)(row0 + ar) * D + kbase + kg * 4;
    const float* zg1 = zg0 + (size_t)64 * D;
    const float* wg  = W + (size_t)ar * D + kbase + kg * 4;
    const int aSts = ar * ROWB + kg * 8;              // bytes (tier-relative)
    const int aSts2 = (ar + 64) * ROWB + kg * 8;
    const int bSts = ar * ROWB + kg * 8;

    // ---- consumer mapping: warp (mw, nw) tile m32 x n16 ----
    const int mw = wid & 3;
    const int nw = wid >> 2;
    const u32 sb = smem_u32(smem1);
    // ldmatrix lane->addr (A, 16x16 f16): row = base + (lane&15), +16B if lane>=16
    const u32 aB = sb + (u32)((mw * 32 + (lane & 15)) * ROWB + (lane >> 4) * 16);
    // (B, n16 x k16): rows n0..n7 lanes0-7(+16B lanes8-15), n8..15 lanes16-23(+16B 24-31)
    const u32 bB = sb + (u32)(B1_OFF + (nw * 16 + (lane & 7) + ((lane >> 4) << 3)) * ROWB
                              + (((lane >> 3) & 1) * 16));

    float acc[2][2][4];  // [m16 slab][n8 block][regs]
#pragma unroll
    for (int i = 0; i < 2; ++i)
#pragma unroll
        for (int j = 0; j < 2; ++j)
#pragma unroll
            for (int q = 0; q < 4; ++q) acc[i][j][q] = 0.f;

    float4 va0, va1, vb;

#define LDG_STAGE(t)                                        \
    do {                                                    \
        va0 = *(const float4*)(zg0 + (t) * BK);             \
        va1 = *(const float4*)(zg1 + (t) * BK);             \
        vb  = *(const float4*)(wg  + (t) * BK);             \
    } while (0)

#define STS_STAGE(buf)                                      \
    do {                                                    \
        char* s_ = smem1 + (buf) * STG_B;                   \
        uint2 t1, t2;                                       \
        split_pack(va0, t1, t2);                            \
        *(uint2*)(s_ + A1_OFF + aSts)  = t1;                \
        *(uint2*)(s_ + A2_OFF + aSts)  = t2;                \
        split_pack(va1, t1, t2);                            \
        *(uint2*)(s_ + A1_OFF + aSts2) = t1;                \
        *(uint2*)(s_ + A2_OFF + aSts2) = t2;                \
        float4 vbs = make_float4(vb.x * 64.f, vb.y * 64.f,  \
                                 vb.z * 64.f, vb.w * 64.f); \
        split_pack(vbs, t1, t2);                            \
        *(uint2*)(s_ + B1_OFF + bSts)  = t1;                \
        *(uint2*)(s_ + B2_OFF + bSts)  = t2;                \
    } while (0)

    LDG_STAGE(0);
    STS_STAGE(0);
    __syncthreads();

    for (int t = 0; t < NSTG; ++t) {
        const int cur = t & 1;
        const bool has_next = (t + 1 < NSTG);
        if (has_next) LDG_STAGE(t + 1);

        const u32 so = (u32)(cur * STG_B);
#pragma unroll
        for (int kc = 0; kc < 2; ++kc) {
            const u32 ko = kc * 32;  // 16 halfs
            u32 b1r[4], b2r[4];
            ldsm4(b1r, bB + so + ko);                 // tier1: {b0 n0-7, b1 n0-7, b0 n8-15, b1 n8-15}
            ldsm4(b2r, bB + so + ko + (B2_OFF - B1_OFF));
#pragma unroll
            for (int ms = 0; ms < 2; ++ms) {
                const u32 mo = (u32)(ms * 16 * ROWB);
                u32 a1r[4], a2r[4];
                ldsm4(a1r, aB + so + mo + ko);
                ldsm4(a2r, aB + so + mo + ko + A2_OFF);
                mma16(acc[ms][0], a1r, b1r[0], b1r[1]);
                mma16(acc[ms][0], a1r, b2r[0], b2r[1]);
                mma16(acc[ms][0], a2r, b1r[0], b1r[1]);
                mma16(acc[ms][1], a1r, b1r[2], b1r[3]);
                mma16(acc[ms][1], a1r, b2r[2], b2r[3]);
                mma16(acc[ms][1], a2r, b1r[2], b1r[3]);
            }
        }

        if (has_next) STS_STAGE(1 - cur);
        __syncthreads();
    }

    // ---- write partial logits (scaled by 64) to scratch ----
    float* gp = g_part + (size_t)ks * NROWS * Kc;
    const int rr = lane >> 2;
    const int cc = (lane & 3) * 2;
#pragma unroll
    for (int ms = 0; ms < 2; ++ms) {
        const int row = row0 + mw * 32 + ms * 16 + rr;
#pragma unroll
        for (int nb = 0; nb < 2; ++nb) {
            const int col = nw * 16 + nb * 8 + cc;
            *(float2*)(gp + (size_t)row * Kc + col) =
                make_float2(acc[ms][nb][0], acc[ms][nb][1]);
            *(float2*)(gp + (size_t)(row + 8) * Kc + col) =
                make_float2(acc[ms][nb][2], acc[ms][nb][3]);
        }
    }
#undef LDG_STAGE
#undef STS_STAGE
}

// ---- kernel 2: reduce + bias + top-k + softmax (warp per row) ----
__global__ __launch_bounds__(256, 8) void router_topk_kernel(
    const float* __restrict__ b, const int* __restrict__ kptr,
    float* __restrict__ out)
{
    const int wid = threadIdx.x >> 5;
    const int lane = threadIdx.x & 31;
    const int row = blockIdx.x * 8 + wid;
    const int c0 = lane * 2;

    const float2 p0 = *(const float2*)(g_part + (size_t)row * Kc + c0);
    const float2 p1 = *(const float2*)(g_part + (size_t)(NROWS + row) * Kc + c0);
    float v0 = (p0.x + p1.x) * 0.015625f + b[c0];
    float v1 = (p0.y + p1.y) * 0.015625f + b[c0 + 1];

    int kk = kptr ? *kptr : 2;
    if (kk < 1) kk = 1;
    if (kk > Kc) kk = Kc;

    unsigned sel = 0;
    float m = 0.f;
    for (int p = 0; p < kk; ++p) {
        float bv = (sel & 1) ? -3.4e38f : v0;
        int bi = c0;
        const float c1v = (sel & 2) ? -3.4e38f : v1;
        if (c1v > bv) { bv = c1v; bi = c0 + 1; }
#pragma unroll
        for (int off = 16; off; off >>= 1) {
            const float ov = __shfl_xor_sync(0xffffffffu, bv, off);
            const int oi = __shfl_xor_sync(0xffffffffu, bi, off);
            if (ov > bv || (ov == bv && oi < bi)) { bv = ov; bi = oi; }
        }
        if (p == 0) m = bv;
        if ((bi >> 1) == lane) sel |= 1u << (bi & 1);
    }

    const float e0 = (sel & 1) ? expf(v0 - m) : 0.f;
    const float e1 = (sel & 2) ? expf(v1 - m) : 0.f;
    float s = e0 + e1;
#pragma unroll
    for (int off = 16; off; off >>= 1) s += __shfl_xor_sync(0xffffffffu, s, off);
    const float inv = 1.0f / s;
    *(float2*)(out + (size_t)row * Kc + c0) = make_float2(e0 * inv, e1 * inv);
}

extern "C" void kernel_launch(void* const* d_in, const int* in_sizes, int n_in,
                              void* d_out, int out_size) {
    const float* z = (const float*)d_in[0];
    const float* W = (const float*)d_in[1];
    const float* b = (const float*)d_in[2];
    const int* kp = (n_in > 3) ? (const int*)d_in[3] : nullptr;
    float* out = (float*)d_out;

    static bool attr_set = false;
    if (!attr_set) {
        cudaFuncSetAttribute(router_gemm_kernel,
                             cudaFuncAttributeMaxDynamicSharedMemorySize, SMEM1);
        attr_set = true;
    }

    const int N = in_sizes[0] / D;                 // 8192
    router_gemm_kernel<<<(N / BM) * KSPLIT, NT1, SMEM1>>>(z, W);
    router_topk_kernel<<<N / 8, 256>>>(b, kp, out);
    (void)out_size;
}

// round 7
// speedup vs baseline: 6.1630x; 1.2226x over previous
#include <cuda_runtime.h>
#include <cuda_fp16.h>
#include <cstdint>

// Router: alpha = softmax(topk_mask(z @ W^T + b))
// z:[8192,4096]f32  W:[64,4096]f32  b:[64]f32  k=2
// K1: split-K(4) GEMM, fp16 2-tier split (z=z1+z2, 64W=w1+w2),
//     mma.sync m16n8k16 f16->f32, partials to scratch.
// K2: reduce 4 partials, *1/64, +bias, top-k mask, softmax.

namespace {
typedef uint32_t u32;
constexpr int D = 4096;
constexpr int KSPLIT = 4;
constexpr int KH = D / KSPLIT;       // 1024
constexpr int BM = 64;
constexpr int BK = 32;
constexpr int NSTG = KH / BK;        // 32
constexpr int NT1 = 256;             // 8 warps
constexpr int Kc = 64;
constexpr int NROWS = 8192;

// tile row = 32 halfs + 8 pad = 80B -> ldmatrix rows conflict-free
constexpr int ROWB = 80;
constexpr int A1_OFF = 0;            // 64*80 = 5120B per tier
constexpr int A2_OFF = 5120;
constexpr int B1_OFF = 10240;
constexpr int B2_OFF = 15360;
constexpr int STG_B = 20480;
constexpr int SMEM1 = 2 * STG_B;     // 40960 (< 48KB default)

__device__ float g_part[KSPLIT * NROWS * Kc];  // 8MB scratch

__device__ __forceinline__ void mma16(float* d, const u32* a, u32 b0, u32 b1) {
    asm volatile(
        "mma.sync.aligned.m16n8k16.row.col.f32.f16.f16.f32 "
        "{%0,%1,%2,%3}, {%4,%5,%6,%7}, {%8,%9}, {%0,%1,%2,%3};"
        : "+f"(d[0]), "+f"(d[1]), "+f"(d[2]), "+f"(d[3])
        : "r"(a[0]), "r"(a[1]), "r"(a[2]), "r"(a[3]), "r"(b0), "r"(b1));
}
__device__ __forceinline__ void ldsm4(u32* r, u32 addr) {
    asm volatile(
        "ldmatrix.sync.aligned.m8n8.x4.shared.b16 {%0,%1,%2,%3}, [%4];"
        : "=r"(r[0]), "=r"(r[1]), "=r"(r[2]), "=r"(r[3]) : "r"(addr));
}
__device__ __forceinline__ u32 smem_u32(const void* p) {
    u32 a;
    asm("{ .reg .u64 t; cvta.to.shared.u64 t, %1; cvt.u32.u64 %0, t; }"
        : "=r"(a) : "l"(p));
    return a;
}
// 2-tier split: h1 = rn(v), h2 = rn(v - h1); v = h1 + h2 + O(2^-22 |v|)
__device__ __forceinline__ void split_pack(float4 v, uint2& t1, uint2& t2) {
    __half hx = __float2half_rn(v.x), hy = __float2half_rn(v.y),
           hz = __float2half_rn(v.z), hw = __float2half_rn(v.w);
    float rx = v.x - __half2float(hx), ry = v.y - __half2float(hy),
          rz = v.z - __half2float(hz), rw = v.w - __half2float(hw);
    __half lx = __float2half_rn(rx), ly = __float2half_rn(ry),
           lz = __float2half_rn(rz), lw = __float2half_rn(rw);
    t1.x = (u32)__half_as_ushort(hx) | ((u32)__half_as_ushort(hy) << 16);
    t1.y = (u32)__half_as_ushort(hz) | ((u32)__half_as_ushort(hw) << 16);
    t2.x = (u32)__half_as_ushort(lx) | ((u32)__half_as_ushort(ly) << 16);
    t2.y = (u32)__half_as_ushort(lz) | ((u32)__half_as_ushort(lw) << 16);
}
} // namespace

__global__ __launch_bounds__(NT1, 4) void router_gemm_kernel(
    const float* __restrict__ z, const float* __restrict__ W)
{
    __shared__ __align__(16) char smem1[SMEM1];

    const int tid = threadIdx.x;
    const int wid = tid >> 5;
    const int lane = tid & 31;
    const int rb = blockIdx.x >> 2;       // row block (0..127)
    const int ks = blockIdx.x & 3;        // k quarter
    const int row0 = rb * BM;
    const int kbase = ks * KH;

    // ---- producer mapping: rows ar, ar+32 of both A and B ----
    const int ar = tid >> 3;              // 0..31
    const int kg = tid & 7;
    const float* zg0 = z + (size_t)(row0 + ar) * D + kbase + kg * 4;
    const float* zg1 = zg0 + (size_t)32 * D;
    const float* wg0 = W + (size_t)ar * D + kbase + kg * 4;
    const float* wg1 = wg0 + (size_t)32 * D;
    const int sts0 = ar * ROWB + kg * 8;
    const int sts1 = (ar + 32) * ROWB + kg * 8;

    // ---- consumer mapping: warp (mw in 0..1, nw in 0..3), tile m32 x n16 ----
    const int mw = wid & 1;
    const int nw = wid >> 1;
    const u32 sb = smem_u32(smem1);
    const u32 aB = sb + (u32)((mw * 32 + (lane & 15)) * ROWB + (lane >> 4) * 16);
    const u32 bB = sb + (u32)(B1_OFF + (nw * 16 + (lane & 7) + ((lane >> 4) << 3)) * ROWB
                              + (((lane >> 3) & 1) * 16));

    float acc[2][2][4];
#pragma unroll
    for (int i = 0; i < 2; ++i)
#pragma unroll
        for (int j = 0; j < 2; ++j)
#pragma unroll
            for (int q = 0; q < 4; ++q) acc[i][j][q] = 0.f;

    float4 va0, va1, vb0, vb1;

#define LDG_STAGE(t)                                        \
    do {                                                    \
        va0 = *(const float4*)(zg0 + (t) * BK);             \
        va1 = *(const float4*)(zg1 + (t) * BK);             \
        vb0 = *(const float4*)(wg0 + (t) * BK);             \
        vb1 = *(const float4*)(wg1 + (t) * BK);             \
    } while (0)

#define STS_STAGE(buf)                                      \
    do {                                                    \
        char* s_ = smem1 + (buf) * STG_B;                   \
        uint2 t1, t2;                                       \
        split_pack(va0, t1, t2);                            \
        *(uint2*)(s_ + A1_OFF + sts0) = t1;                 \
        *(uint2*)(s_ + A2_OFF + sts0) = t2;                 \
        split_pack(va1, t1, t2);                            \
        *(uint2*)(s_ + A1_OFF + sts1) = t1;                 \
        *(uint2*)(s_ + A2_OFF + sts1) = t2;                 \
        float4 w0 = make_float4(vb0.x * 64.f, vb0.y * 64.f, \
                                vb0.z * 64.f, vb0.w * 64.f);\
        split_pack(w0, t1, t2);                             \
        *(uint2*)(s_ + B1_OFF + sts0) = t1;                 \
        *(uint2*)(s_ + B2_OFF + sts0) = t2;                 \
        float4 w1 = make_float4(vb1.x * 64.f, vb1.y * 64.f, \
                                vb1.z * 64.f, vb1.w * 64.f);\
        split_pack(w1, t1, t2);                             \
        *(uint2*)(s_ + B1_OFF + sts1) = t1;                 \
        *(uint2*)(s_ + B2_OFF + sts1) = t2;                 \
    } while (0)

    LDG_STAGE(0);
    STS_STAGE(0);
    __syncthreads();

    for (int t = 0; t < NSTG; ++t) {
        const int cur = t & 1;
        const bool has_next = (t + 1 < NSTG);
        if (has_next) LDG_STAGE(t + 1);

        const u32 so = (u32)(cur * STG_B);
#pragma unroll
        for (int kc = 0; kc < 2; ++kc) {
            const u32 ko = kc * 32;  // 16 halfs
            u32 b1r[4], b2r[4];
            ldsm4(b1r, bB + so + ko);
            ldsm4(b2r, bB + so + ko + (B2_OFF - B1_OFF));
#pragma unroll
            for (int ms = 0; ms < 2; ++ms) {
                const u32 mo = (u32)(ms * 16 * ROWB);
                u32 a1r[4], a2r[4];
                ldsm4(a1r, aB + so + mo + ko);
                ldsm4(a2r, aB + so + mo + ko + A2_OFF);
                mma16(acc[ms][0], a1r, b1r[0], b1r[1]);
                mma16(acc[ms][0], a1r, b2r[0], b2r[1]);
                mma16(acc[ms][0], a2r, b1r[0], b1r[1]);
                mma16(acc[ms][1], a1r, b1r[2], b1r[3]);
                mma16(acc[ms][1], a1r, b2r[2], b2r[3]);
                mma16(acc[ms][1], a2r, b1r[2], b1r[3]);
            }
        }

        if (has_next) STS_STAGE(1 - cur);
        __syncthreads();
    }

    // ---- write partial logits (scaled by 64) ----
    float* gp = g_part + (size_t)ks * NROWS * Kc;
    const int rr = lane >> 2;
    const int cc = (lane & 3) * 2;
#pragma unroll
    for (int ms = 0; ms < 2; ++ms) {
        const int row = row0 + mw * 32 + ms * 16 + rr;
#pragma unroll
        for (int nb = 0; nb < 2; ++nb) {
            const int col = nw * 16 + nb * 8 + cc;
            *(float2*)(gp + (size_t)row * Kc + col) =
                make_float2(acc[ms][nb][0], acc[ms][nb][1]);
            *(float2*)(gp + (size_t)(row + 8) * Kc + col) =
                make_float2(acc[ms][nb][2], acc[ms][nb][3]);
        }
    }
#undef LDG_STAGE
#undef STS_STAGE
}

// ---- K2: reduce partials + bias + top-k + softmax (warp per row) ----
__global__ __launch_bounds__(256, 8) void router_topk_kernel(
    const float* __restrict__ b, const int* __restrict__ kptr,
    float* __restrict__ out)
{
    const int wid = threadIdx.x >> 5;
    const int lane = threadIdx.x & 31;
    const int row = blockIdx.x * 8 + wid;
    const int c0 = lane * 2;

    float v0 = 0.f, v1 = 0.f;
#pragma unroll
    for (int ks = 0; ks < KSPLIT; ++ks) {
        const float2 p = *(const float2*)(
            g_part + (size_t)ks * NROWS * Kc + (size_t)row * Kc + c0);
        v0 += p.x;
        v1 += p.y;
    }
    v0 = v0 * 0.015625f + b[c0];
    v1 = v1 * 0.015625f + b[c0 + 1];

    int kk = kptr ? *kptr : 2;
    if (kk < 1) kk = 1;
    if (kk > Kc) kk = Kc;

    unsigned sel = 0;
    float m = 0.f;
    for (int p = 0; p < kk; ++p) {
        float bv = (sel & 1) ? -3.4e38f : v0;
        int bi = c0;
        const float c1v = (sel & 2) ? -3.4e38f : v1;
        if (c1v > bv) { bv = c1v; bi = c0 + 1; }
#pragma unroll
        for (int off = 16; off; off >>= 1) {
            const float ov = __shfl_xor_sync(0xffffffffu, bv, off);
            const int oi = __shfl_xor_sync(0xffffffffu, bi, off);
            if (ov > bv || (ov == bv && oi < bi)) { bv = ov; bi = oi; }
        }
        if (p == 0) m = bv;
        if ((bi >> 1) == lane) sel |= 1u << (bi & 1);
    }

    const float e0 = (sel & 1) ? expf(v0 - m) : 0.f;
    const float e1 = (sel & 2) ? expf(v1 - m) : 0.f;
    float s = e0 + e1;
#pragma unroll
    for (int off = 16; off; off >>= 1) s += __shfl_xor_sync(0xffffffffu, s, off);
    const float inv = 1.0f / s;
    *(float2*)(out + (size_t)row * Kc + c0) = make_float2(e0 * inv, e1 * inv);
}

extern "C" void kernel_launch(void* const* d_in, const int* in_sizes, int n_in,
                              void* d_out, int out_size) {
    const float* z = (const float*)d_in[0];
    const float* W = (const float*)d_in[1];
    const float* b = (const float*)d_in[2];
    const int* kp = (n_in > 3) ? (const int*)d_in[3] : nullptr;
    float* out = (float*)d_out;

    const int N = in_sizes[0] / D;                     // 8192
    router_gemm_kernel<<<(N / BM) * KSPLIT, NT1>>>(z, W);
    router_topk_kernel<<<N / 8, 256>>>(b, kp, out);
    (void)out_size;
}

// round 8
// speedup vs baseline: 6.7931x; 1.1022x over previous
#include <cuda_runtime.h>
#include <cuda_fp16.h>
#include <cstdint>

// Router: alpha = softmax(topk_mask(z @ W^T + b))
// z:[8192,4096]f32  W:[64,4096]f32  b:[64]f32  k=2
// K1: split-K(8) GEMM, fp16 2-tier split (z=z1+z2, 64W=w1+w2),
//     mma.sync m16n8k16, 3-stage smem ring, LDG prefetch distance 2.
// K2: reduce 8 partials, *1/64, +bias, top-k mask, softmax (top-2 fast path).

namespace {
typedef uint32_t u32;
constexpr int D = 4096;
constexpr int KSPLIT = 8;
constexpr int KH = D / KSPLIT;       // 512
constexpr int BM = 64;
constexpr int BK = 32;
constexpr int NSTG = KH / BK;        // 16
constexpr int NT1 = 256;             // 8 warps
constexpr int Kc = 64;
constexpr int NROWS = 8192;

// tile row = 32 halfs + 8 pad = 80B -> ldmatrix rows conflict-free
constexpr int ROWB = 80;
constexpr int A1_OFF = 0;            // 64*80 = 5120B per tier
constexpr int A2_OFF = 5120;
constexpr int B1_OFF = 10240;
constexpr int B2_OFF = 15360;
constexpr int STG_B = 20480;
constexpr int SMEM1 = 3 * STG_B;     // 61440 (dynamic)

__device__ float g_part[KSPLIT * NROWS * Kc];  // 16MB scratch

__device__ __forceinline__ void mma16(float* d, const u32* a, u32 b0, u32 b1) {
    asm volatile(
        "mma.sync.aligned.m16n8k16.row.col.f32.f16.f16.f32 "
        "{%0,%1,%2,%3}, {%4,%5,%6,%7}, {%8,%9}, {%0,%1,%2,%3};"
        : "+f"(d[0]), "+f"(d[1]), "+f"(d[2]), "+f"(d[3])
        : "r"(a[0]), "r"(a[1]), "r"(a[2]), "r"(a[3]), "r"(b0), "r"(b1));
}
__device__ __forceinline__ void ldsm4(u32* r, u32 addr) {
    asm volatile(
        "ldmatrix.sync.aligned.m8n8.x4.shared.b16 {%0,%1,%2,%3}, [%4];"
        : "=r"(r[0]), "=r"(r[1]), "=r"(r[2]), "=r"(r[3]) : "r"(addr));
}
__device__ __forceinline__ u32 smem_u32(const void* p) {
    u32 a;
    asm("{ .reg .u64 t; cvta.to.shared.u64 t, %1; cvt.u32.u64 %0, t; }"
        : "=r"(a) : "l"(p));
    return a;
}
// 2-tier split: h1 = rn(v), h2 = rn(v - h1); v = h1 + h2 + O(2^-22 |v|)
__device__ __forceinline__ void split_pack(float4 v, uint2& t1, uint2& t2) {
    __half hx = __float2half_rn(v.x), hy = __float2half_rn(v.y),
           hz = __float2half_rn(v.z), hw = __float2half_rn(v.w);
    float rx = v.x - __half2float(hx), ry = v.y - __half2float(hy),
          rz = v.z - __half2float(hz), rw = v.w - __half2float(hw);
    __half lx = __float2half_rn(rx), ly = __float2half_rn(ry),
           lz = __float2half_rn(rz), lw = __float2half_rn(rw);
    t1.x = (u32)__half_as_ushort(hx) | ((u32)__half_as_ushort(hy) << 16);
    t1.y = (u32)__half_as_ushort(hz) | ((u32)__half_as_ushort(hw) << 16);
    t2.x = (u32)__half_as_ushort(lx) | ((u32)__half_as_ushort(ly) << 16);
    t2.y = (u32)__half_as_ushort(lz) | ((u32)__half_as_ushort(lw) << 16);
}
} // namespace

extern __shared__ __align__(16) char smem1[];

__global__ __launch_bounds__(NT1, 3) void router_gemm_kernel(
    const float* __restrict__ z, const float* __restrict__ W)
{
    const int tid = threadIdx.x;
    const int wid = tid >> 5;
    const int lane = tid & 31;
    const int rb = blockIdx.x >> 3;       // row block (0..127)
    const int ks = blockIdx.x & 7;        // k eighth
    const int row0 = rb * BM;
    const int kbase = ks * KH;

    // ---- producer mapping: rows ar, ar+32 of both A and B ----
    const int ar = tid >> 3;              // 0..31
    const int kg = tid & 7;
    const float* zg0 = z + (size_t)(row0 + ar) * D + kbase + kg * 4;
    const float* zg1 = zg0 + (size_t)32 * D;
    const float* wg0 = W + (size_t)ar * D + kbase + kg * 4;
    const float* wg1 = wg0 + (size_t)32 * D;
    const int sts0 = ar * ROWB + kg * 8;
    const int sts1 = (ar + 32) * ROWB + kg * 8;

    // ---- consumer mapping: warp (mw 0..1, nw 0..3), tile m32 x n16 ----
    const int mw = wid & 1;
    const int nw = wid >> 1;
    const u32 sb = smem_u32(smem1);
    const u32 aB = sb + (u32)((mw * 32 + (lane & 15)) * ROWB + (lane >> 4) * 16);
    const u32 bB = sb + (u32)(B1_OFF + (nw * 16 + (lane & 7) + ((lane >> 4) << 3)) * ROWB
                              + (((lane >> 3) & 1) * 16));

    float acc[2][2][4];
#pragma unroll
    for (int i = 0; i < 2; ++i)
#pragma unroll
        for (int j = 0; j < 2; ++j)
#pragma unroll
            for (int q = 0; q < 4; ++q) acc[i][j][q] = 0.f;

    float4 va0, va1, vb0, vb1;

#define LDG_STAGE(t)                                        \
    do {                                                    \
        va0 = *(const float4*)(zg0 + (t) * BK);             \
        va1 = *(const float4*)(zg1 + (t) * BK);             \
        vb0 = *(const float4*)(wg0 + (t) * BK);             \
        vb1 = *(const float4*)(wg1 + (t) * BK);             \
    } while (0)

#define STS_STAGE(buf)                                      \
    do {                                                    \
        char* s_ = smem1 + (buf) * STG_B;                   \
        uint2 t1, t2;                                       \
        split_pack(va0, t1, t2);                            \
        *(uint2*)(s_ + A1_OFF + sts0) = t1;                 \
        *(uint2*)(s_ + A2_OFF + sts0) = t2;                 \
        split_pack(va1, t1, t2);                            \
        *(uint2*)(s_ + A1_OFF + sts1) = t1;                 \
        *(uint2*)(s_ + A2_OFF + sts1) = t2;                 \
        float4 w0 = make_float4(vb0.x * 64.f, vb0.y * 64.f, \
                                vb0.z * 64.f, vb0.w * 64.f);\
        split_pack(w0, t1, t2);                             \
        *(uint2*)(s_ + B1_OFF + sts0) = t1;                 \
        *(uint2*)(s_ + B2_OFF + sts0) = t2;                 \
        float4 w1 = make_float4(vb1.x * 64.f, vb1.y * 64.f, \
                                vb1.z * 64.f, vb1.w * 64.f);\
        split_pack(w1, t1, t2);                             \
        *(uint2*)(s_ + B1_OFF + sts1) = t1;                 \
        *(uint2*)(s_ + B2_OFF + sts1) = t2;                 \
    } while (0)

    // ---- preamble: fill buffers 0,1; LDG(2) in flight ----
    LDG_STAGE(0);
    STS_STAGE(0);
    LDG_STAGE(1);
    STS_STAGE(1);
    LDG_STAGE(2);
    __syncthreads();

#pragma unroll
    for (int t = 0; t < NSTG; ++t) {
        const u32 so = (u32)((t % 3) * STG_B);
#pragma unroll
        for (int kc = 0; kc < 2; ++kc) {
            const u32 ko = kc * 32;  // 16 halfs
            u32 b1r[4], b2r[4];
            ldsm4(b1r, bB + so + ko);
            ldsm4(b2r, bB + so + ko + (B2_OFF - B1_OFF));
#pragma unroll
            for (int ms = 0; ms < 2; ++ms) {
                const u32 mo = (u32)(ms * 16 * ROWB);
                u32 a1r[4], a2r[4];
                ldsm4(a1r, aB + so + mo + ko);
                ldsm4(a2r, aB + so + mo + ko + A2_OFF);
                mma16(acc[ms][0], a1r, b1r[0], b1r[1]);
                mma16(acc[ms][0], a1r, b2r[0], b2r[1]);
                mma16(acc[ms][0], a2r, b1r[0], b1r[1]);
                mma16(acc[ms][1], a1r, b1r[2], b1r[3]);
                mma16(acc[ms][1], a1r, b2r[2], b2r[3]);
                mma16(acc[ms][1], a2r, b1r[2], b1r[3]);
            }
        }

        // STS tile t+2 (regs from LDG(t+2), issued one stage ago);
        // then refill regs with LDG(t+3): a full stage of latency slack.
        if (t + 2 < NSTG) STS_STAGE((t + 2) % 3);
        if (t + 3 < NSTG) LDG_STAGE(t + 3);
        __syncthreads();
    }

    // ---- write partial logits (scaled by 64) ----
    float* gp = g_part + (size_t)ks * NROWS * Kc;
    const int rr = lane >> 2;
    const int cc = (lane & 3) * 2;
#pragma unroll
    for (int ms = 0; ms < 2; ++ms) {
        const int row = row0 + mw * 32 + ms * 16 + rr;
#pragma unroll
        for (int nb = 0; nb < 2; ++nb) {
            const int col = nw * 16 + nb * 8 + cc;
            *(float2*)(gp + (size_t)row * Kc + col) =
                make_float2(acc[ms][nb][0], acc[ms][nb][1]);
            *(float2*)(gp + (size_t)(row + 8) * Kc + col) =
                make_float2(acc[ms][nb][2], acc[ms][nb][3]);
        }
    }
#undef LDG_STAGE
#undef STS_STAGE
}

// ---- K2: reduce partials + bias + top-k + softmax (warp per row) ----
__global__ __launch_bounds__(256, 8) void router_topk_kernel(
    const float* __restrict__ b, const int* __restrict__ kptr,
    float* __restrict__ out)
{
    const int wid = threadIdx.x >> 5;
    const int lane = threadIdx.x & 31;
    const int row = blockIdx.x * 8 + wid;
    const int c0 = lane * 2;

    float v0 = 0.f, v1 = 0.f;
#pragma unroll
    for (int ks = 0; ks < KSPLIT; ++ks) {
        const float2 p = *(const float2*)(
            g_part + (size_t)ks * NROWS * Kc + (size_t)row * Kc + c0);
        v0 += p.x;
        v1 += p.y;
    }
    v0 = v0 * 0.015625f + b[c0];
    v1 = v1 * 0.015625f + b[c0 + 1];

    int kk = kptr ? *kptr : 2;
    if (kk < 1) kk = 1;
    if (kk > Kc) kk = Kc;

    if (kk == 2) {
        // one-pass top-2: lane-local sorted pair, butterfly merge.
        // order: (val desc, idx asc) — matches jax.lax.top_k tie-break.
        float hv, lv;
        int hi_, li_;
        if (v1 > v0) { hv = v1; hi_ = c0 + 1; lv = v0; li_ = c0; }
        else         { hv = v0; hi_ = c0;     lv = v1; li_ = c0 + 1; }
#pragma unroll
        for (int off = 16; off; off >>= 1) {
            const float ohv = __shfl_xor_sync(0xffffffffu, hv, off);
            const float olv = __shfl_xor_sync(0xffffffffu, lv, off);
            const int ohi = __shfl_xor_sync(0xffffffffu, hi_, off);
            const int oli = __shfl_xor_sync(0xffffffffu, li_, off);
            const bool h1win = (hv > ohv) || (hv == ohv && hi_ < ohi);
            const float whv = h1win ? hv : ohv;   // merged hi
            const int   whi = h1win ? hi_ : ohi;
            const float lsv = h1win ? ohv : hv;   // loser's hi
            const int   lsi = h1win ? ohi : hi_;
            const float wlv = h1win ? lv : olv;   // winner's lo
            const int   wli = h1win ? li_ : oli;
            const bool sw = (lsv > wlv) || (lsv == wlv && lsi < wli);
            hv = whv; hi_ = whi;
            lv = sw ? lsv : wlv;
            li_ = sw ? lsi : wli;
        }
        const float elo = expf(lv - hv);
        const float inv = 1.0f / (1.0f + elo);
        const float eli = elo * inv;
        const float o0 = (c0 == hi_) ? inv : ((c0 == li_) ? eli : 0.f);
        const float o1 = (c0 + 1 == hi_) ? inv : ((c0 + 1 == li_) ? eli : 0.f);
        *(float2*)(out + (size_t)row * Kc + c0) = make_float2(o0, o1);
        return;
    }

    // generic k path
    unsigned sel = 0;
    float m = 0.f;
    for (int p = 0; p < kk; ++p) {
        float bv = (sel & 1) ? -3.4e38f : v0;
        int bi = c0;
        const float c1v = (sel & 2) ? -3.4e38f : v1;
        if (c1v > bv) { bv = c1v; bi = c0 + 1; }
#pragma unroll
        for (int off = 16; off; off >>= 1) {
            const float ov = __shfl_xor_sync(0xffffffffu, bv, off);
            const int oi = __shfl_xor_sync(0xffffffffu, bi, off);
            if (ov > bv || (ov == bv && oi < bi)) { bv = ov; bi = oi; }
        }
        if (p == 0) m = bv;
        if ((bi >> 1) == lane) sel |= 1u << (bi & 1);
    }
    const float e0 = (sel & 1) ? expf(v0 - m) : 0.f;
    const float e1 = (sel & 2) ? expf(v1 - m) : 0.f;
    float s = e0 + e1;
#pragma unroll
    for (int off = 16; off; off >>= 1) s += __shfl_xor_sync(0xffffffffu, s, off);
    const float inv = 1.0f / s;
    *(float2*)(out + (size_t)row * Kc + c0) = make_float2(e0 * inv, e1 * inv);
}

extern "C" void kernel_launch(void* const* d_in, const int* in_sizes, int n_in,
                              void* d_out, int out_size) {
    const float* z = (const float*)d_in[0];
    const float* W = (const float*)d_in[1];
    const float* b = (const float*)d_in[2];
    const int* kp = (n_in > 3) ? (const int*)d_in[3] : nullptr;
    float* out = (float*)d_out;

    cudaFuncSetAttribute(router_gemm_kernel,
                         cudaFuncAttributeMaxDynamicSharedMemorySize, SMEM1);

    const int N = in_sizes[0] / D;                      // 8192
    router_gemm_kernel<<<(N / BM) * KSPLIT, NT1, SMEM1>>>(z, W);
    router_topk_kernel<<<N / 8, 256>>>(b, kp, out);
    (void)out_size;
}